// round 16
// baseline (speedup 1.0000x reference)
#include <cuda_runtime.h>
#include <cstdint>

// Fixed problem shape: (N,C,H,W,T) = (8,16,32,32,500)
//
// FINAL — measured optimum over a 15-round sweep on GB300 (sm_103a):
//   - 128 threads per (c,h,w) row, 2 rows per 256-thread block, 4 batch
//     rows per thread (NPER=4) -> 8 front-batched independent LDG.128
//     (MLP_p1=8, the measured peak of the MLP/occupancy surface).
//   - Pure 32-bit indexing -> 40 regs; __launch_bounds__(256,6) -> 48 warps/SM.
//   - Per-row delay params computed once, amortized over 4 n-rows;
//     warp-uniform extract case r = (-1-floor(delay/Ts)) mod 4.
//   - n-half selector on the HIGH grid bit: wave-concurrent blocks stream one
//     contiguous input slab + one output slab (DRAM page locality, 262 MB
//     concurrent working set ~ TLB reach).
// Measured: 74.2 us kernel / 79.97 us wall, DRAM 80.4% (6.37 TB/s), aggregate
// r+w ~6.55 TB/s == B300 LTS/HBM mixed-stream ceiling. All other axes
// (MLP 16, occ forcing, shfl dedup, ld.cs/st.cs) measured neutral or worse.
constexpr int N_ = 8;
constexpr int C_ = 16;
constexpr int H_ = 32;
constexpr int W_ = 32;
constexpr int T_ = 500;
constexpr int CHW = C_ * H_ * W_;     // 16384 (power of two)
constexpr int TV  = T_ / 4;           // 125 float4 per row
constexpr int NPER = 4;               // batch rows per thread
constexpr int ROWSTRIDE = CHW * TV;   // 2,048,000 float4 stride between n's (32-bit safe)
constexpr int HALF_GRID = CHW / 2;    // 8192 blocks per n-half

__global__ void __launch_bounds__(256, 6) delay_kernel(
    const float* __restrict__ x,
    const float* __restrict__ delay,
    const uint32_t* __restrict__ ts_bits,
    float* __restrict__ out)
{
    // n-half = HIGH bit of blockIdx; chw pair = low bits. 128 threads per chw.
    int tv  = threadIdx.x & 127;
    int bp  = blockIdx.x & (HALF_GRID - 1);          // chw pair index
    int n0  = (blockIdx.x >= HALF_GRID) ? NPER : 0;  // n-half (wave-contiguous)
    int chw = (bp << 1) | (threadIdx.x >> 7);
    if (tv >= TV) return;

    // Decode Ts robustly (scalar may arrive as int32 or float32 bits).
    uint32_t tb = __ldg(ts_bits);
    float tf = __uint_as_float(tb);
    float Ts = (tf >= 1e-6f && tf <= 1e6f) ? tf : (float)(int)tb;

    // Per-chw shift parameters — shared by all n.
    float s    = __ldg(delay + chw) / Ts;
    float sif  = floorf(s);
    float frac = s - sif;
    int   si   = (int)sif;

    int start = -1 - si;         // first tap offset
    int q0 = start >> 2;         // floor-div-4
    int r  = start & 3;          // warp-uniform extract case

    int vi = tv + q0;
    bool va = (vi     >= 0) && (vi     < TV);
    bool vb = (vi + 1 >= 0) && (vi + 1 < TV);

    // Pure 32-bit indexing: total float4 count = 16.384M << 2^31.
    const float4* __restrict__ x4 = reinterpret_cast<const float4*>(x);
    int abase = (n0 * CHW + chw) * TV + vi;

    // Front-batched independent loads: 8 x LDG.128 in flight (MLP_p1 = 8).
    float4 z = make_float4(0.f, 0.f, 0.f, 0.f);
    float4 A[NPER], B[NPER];
#pragma unroll
    for (int j = 0; j < NPER; ++j) {
        A[j] = va ? __ldg(x4 + (abase + j * ROWSTRIDE))     : z;
        B[j] = vb ? __ldg(x4 + (abase + j * ROWSTRIDE + 1)) : z;
    }

    float w1 = frac;
    float w0 = 1.0f - frac;
    float4* __restrict__ o4 = reinterpret_cast<float4*>(out);
    int obase = (n0 * CHW + chw) * TV + tv;

#pragma unroll
    for (int j = 0; j < NPER; ++j) {
        float l0, l1, l2, l3, l4;
        switch (r) {
            case 0: l0 = A[j].x; l1 = A[j].y; l2 = A[j].z; l3 = A[j].w; l4 = B[j].x; break;
            case 1: l0 = A[j].y; l1 = A[j].z; l2 = A[j].w; l3 = B[j].x; l4 = B[j].y; break;
            case 2: l0 = A[j].z; l1 = A[j].w; l2 = B[j].x; l3 = B[j].y; l4 = B[j].z; break;
            default:l0 = A[j].w; l1 = B[j].x; l2 = B[j].y; l3 = B[j].z; l4 = B[j].w; break;
        }
        float4 o;
        o.x = w0 * l1 + w1 * l0;
        o.y = w0 * l2 + w1 * l1;
        o.z = w0 * l3 + w1 * l2;
        o.w = w0 * l4 + w1 * l3;
        o4[obase + j * ROWSTRIDE] = o;
    }
}

extern "C" void kernel_launch(void* const* d_in, const int* in_sizes, int n_in,
                              void* d_out, int out_size)
{
    const float*    x     = (const float*)d_in[0];
    const float*    delay = (const float*)d_in[1];
    const uint32_t* ts    = (const uint32_t*)d_in[2];
    float*          out   = (float*)d_out;

    // CHW blocks: low bits pick the chw pair, high bit picks the n-half.
    delay_kernel<<<CHW, 256>>>(x, delay, ts, out);
}